// round 1
// baseline (speedup 1.0000x reference)
#include <cuda_runtime.h>
#include <cstdint>

#define ROWS 4096
#define COLS 8192
#define KSEL 4096
#define NTHR 512
#define EPT  (COLS / NTHR)   // 16 elements per thread

// gumbel-sigmoid key: fp32 bit pattern of sigmoid((z + g)/T), g = -log(-log(eps)).
// sigmoid output is strictly positive => uint bit compare == float compare.
__device__ __forceinline__ unsigned gm_key(float zi, float ei) {
    const float T = 0.66666668653488159f;       // (float)(2.0/3.0), matches jnp f32 promotion
    float g = -logf(-logf(ei));
    float s = (zi + g) / T;                     // IEEE div, matches reference op
    float m = 1.0f / (1.0f + expf(-s));
    return __float_as_uint(m);
}

__global__ void __launch_bounds__(NTHR)
mask_topk_kernel(const float* __restrict__ z,
                 const float* __restrict__ eps,
                 float* __restrict__ out)
{
    __shared__ unsigned keys[COLS];      // 32 KB
    __shared__ unsigned hist[256];
    __shared__ unsigned wsum[16];
    __shared__ unsigned s_prefix, s_remaining;

    const int tid = threadIdx.x;
    const long long rb = (long long)blockIdx.x * COLS;
    const float* zr  = z   + rb;
    const float* er  = eps + rb;
    float*       orr = out + rb;

    // ---- Phase 1: load (coalesced float4), compute keys into smem ----
    #pragma unroll
    for (int c = 0; c < 4; ++c) {
        int i = (c * NTHR + tid) * 4;
        float4 zv = *reinterpret_cast<const float4*>(zr + i);
        float4 ev = *reinterpret_cast<const float4*>(er + i);
        uint4 kv;
        kv.x = gm_key(zv.x, ev.x);
        kv.y = gm_key(zv.y, ev.y);
        kv.z = gm_key(zv.z, ev.z);
        kv.w = gm_key(zv.w, ev.w);
        *reinterpret_cast<uint4*>(&keys[i]) = kv;   // consecutive 16B, conflict-free
    }
    __syncthreads();

    // ---- Phase 2: 4-pass radix select (descending) for the K-th largest key ----
    unsigned prefix = 0, remaining = KSEL;
    #pragma unroll 1
    for (int p = 0; p < 4; ++p) {
        const int shift = 24 - 8 * p;
        if (tid < 256) hist[tid] = 0;
        __syncthreads();

        const unsigned pm = (p == 0) ? 0u : (0xFFFFFFFFu << (shift + 8));
        #pragma unroll
        for (int j = 0; j < EPT; ++j) {
            unsigned k = keys[tid + j * NTHR];          // stride-512 words: bank-conflict-free
            bool pred = ((k & pm) == prefix);
            unsigned act = __ballot_sync(0xFFFFFFFFu, pred);
            if (pred) {
                unsigned b = (k >> shift) & 255u;
                // warp-aggregated histogram atomic (first digit is exponent-heavy)
                unsigned peers = __match_any_sync(act, b);
                if ((unsigned)(__ffs(peers) - 1) == (unsigned)(tid & 31))
                    atomicAdd(&hist[b], (unsigned)__popc(peers));
            }
        }
        __syncthreads();

        // warp 0: find bucket where descending cumulative count crosses `remaining`
        if (tid < 32) {
            unsigned cnt[8], lsum = 0;
            #pragma unroll
            for (int q = 0; q < 8; ++q) { cnt[q] = hist[255 - tid * 8 - q]; lsum += cnt[q]; }
            unsigned inc = lsum;
            #pragma unroll
            for (int d = 1; d < 32; d <<= 1) {
                unsigned v = __shfl_up_sync(0xFFFFFFFFu, inc, d);
                if (tid >= d) inc += v;
            }
            unsigned excl = inc - lsum;
            if (excl < remaining && inc >= remaining) {   // unique lane
                unsigned run = excl;
                bool found = false;
                #pragma unroll
                for (int q = 0; q < 8; ++q) {
                    if (!found) {
                        if (run + cnt[q] >= remaining) {
                            s_prefix    = prefix | ((unsigned)(255 - tid * 8 - q) << shift);
                            s_remaining = remaining - run;
                            found = true;
                        } else {
                            run += cnt[q];
                        }
                    }
                }
            }
        }
        __syncthreads();
        prefix    = s_prefix;      // safe: next write is 2 barriers away
        remaining = s_remaining;
    }
    const unsigned t = prefix;     // exact bit pattern of K-th largest gm
    // `remaining` = how many keys EQUAL to t to take, lowest indices first

    // ---- Phase 3: stable rank of equal keys (index order == contiguous-chunk order) ----
    unsigned local_eq = 0;
    #pragma unroll
    for (int c = 0; c < 4; ++c) {
        uint4 kv = *reinterpret_cast<const uint4*>(&keys[tid * EPT + c * 4]);
        local_eq += (kv.x == t) + (kv.y == t) + (kv.z == t) + (kv.w == t);
    }
    const int lane = tid & 31, w = tid >> 5;
    unsigned inc = local_eq;
    #pragma unroll
    for (int d = 1; d < 32; d <<= 1) {
        unsigned v = __shfl_up_sync(0xFFFFFFFFu, inc, d);
        if (lane >= d) inc += v;
    }
    if (lane == 31) wsum[w] = inc;
    __syncthreads();
    if (tid < 32) {
        unsigned v = (tid < 16) ? wsum[tid] : 0u;
        #pragma unroll
        for (int d = 1; d < 16; d <<= 1) {
            unsigned u = __shfl_up_sync(0xFFFFFFFFu, v, d);
            if (tid >= d) v += u;
        }
        if (tid < 16) wsum[tid] = v;
    }
    __syncthreads();
    unsigned run = (inc - local_eq) + (w ? wsum[w - 1] : 0u);  // exclusive rank of my first equal

    // ---- Phase 4: emit 0/1 mask (forward value of straight-through estimator) ----
    #pragma unroll
    for (int c = 0; c < 4; ++c) {
        uint4 kv = *reinterpret_cast<const uint4*>(&keys[tid * EPT + c * 4]);
        float4 o;
        o.x = (kv.x > t || (kv.x == t && run < remaining)) ? 1.0f : 0.0f; run += (kv.x == t);
        o.y = (kv.y > t || (kv.y == t && run < remaining)) ? 1.0f : 0.0f; run += (kv.y == t);
        o.z = (kv.z > t || (kv.z == t && run < remaining)) ? 1.0f : 0.0f; run += (kv.z == t);
        o.w = (kv.w > t || (kv.w == t && run < remaining)) ? 1.0f : 0.0f; run += (kv.w == t);
        *reinterpret_cast<float4*>(orr + tid * EPT + c * 4) = o;
    }
}

extern "C" void kernel_launch(void* const* d_in, const int* in_sizes, int n_in,
                              void* d_out, int out_size)
{
    const float* z   = (const float*)d_in[0];   // z_loga  [4096, 8192] f32
    const float* eps = (const float*)d_in[1];   // eps     [4096, 8192] f32
    // d_in[2] = step (unused in training-branch forward)
    float* out = (float*)d_out;                 // [4096, 8192] f32
    (void)in_sizes; (void)n_in; (void)out_size;

    mask_topk_kernel<<<ROWS, NTHR>>>(z, eps, out);
}

// round 2
// speedup vs baseline: 2.1215x; 2.1215x over previous
#include <cuda_runtime.h>
#include <cstdint>

#define ROWS 4096
#define COLS 8192
#define KSEL 4096
#define NTHR 512
#define EPT  (COLS / NTHR)   // 16 elements per thread

// Monotone uint transform of a signed float: order(u) == order(f).
__device__ __forceinline__ unsigned ord_key(float f) {
    unsigned b = __float_as_uint(f);
    return b ^ (((unsigned)((int)b >> 31)) | 0x80000000u);
}

// Selection key: s = z + gumbel, gumbel = -log(-log(eps)).
// sigmoid(s/T) is strictly monotone in s, so top-K on s == top-K on gm
// (up to fp32-gm ties, which are ~1e-4 probability per row at the boundary).
__device__ __forceinline__ unsigned gm_key(float zi, float ei) {
    float g = -logf(-logf(ei));     // accurate logf: ordering fidelity ~1 ulp
    return ord_key(zi + g);
}

// Find the bin (descending order) where cumulative count crosses `rem`.
// Writes selected bin and residual remaining into s_bin / s_rem.
template<int NBINS>
__device__ __forceinline__ void select_bin(const unsigned* __restrict__ hist,
                                           unsigned rem,
                                           unsigned* wsum,
                                           unsigned* s_bin, unsigned* s_rem,
                                           int tid)
{
    constexpr int BPT = NBINS / NTHR;
    unsigned cnt[BPT], lsum = 0;
    #pragma unroll
    for (int q = 0; q < BPT; ++q) {
        cnt[q] = hist[NBINS - 1 - tid * BPT - q];
        lsum += cnt[q];
    }
    const int lane = tid & 31, w = tid >> 5;
    unsigned inc = lsum;
    #pragma unroll
    for (int d = 1; d < 32; d <<= 1) {
        unsigned v = __shfl_up_sync(0xFFFFFFFFu, inc, d);
        if (lane >= d) inc += v;
    }
    if (lane == 31) wsum[w] = inc;
    __syncthreads();
    if (tid < 32) {
        unsigned v = (tid < 16) ? wsum[tid] : 0u;
        #pragma unroll
        for (int d = 1; d < 16; d <<= 1) {
            unsigned u = __shfl_up_sync(0xFFFFFFFFu, v, d);
            if (tid >= d) v += u;
        }
        if (tid < 16) wsum[tid] = v;
    }
    __syncthreads();
    unsigned excl = (inc - lsum) + (w ? wsum[w - 1] : 0u);
    if (excl < rem && excl + lsum >= rem) {       // exactly one thread
        unsigned run = excl;
        bool found = false;
        #pragma unroll
        for (int q = 0; q < BPT; ++q) {
            if (!found) {
                if (run + cnt[q] >= rem) {
                    *s_bin = (unsigned)(NBINS - 1 - tid * BPT - q);
                    *s_rem = rem - run;
                    found = true;
                } else {
                    run += cnt[q];
                }
            }
        }
    }
    __syncthreads();
}

__global__ void __launch_bounds__(NTHR, 4)
mask_topk_kernel(const float* __restrict__ z,
                 const float* __restrict__ eps,
                 float* __restrict__ out)
{
    __shared__ unsigned keys[COLS];      // 32 KB
    __shared__ unsigned hist[2048];      // 8 KB
    __shared__ unsigned wsum[16];
    __shared__ unsigned s_bin, s_rem;

    const int tid = threadIdx.x;
    const long long rb = (long long)blockIdx.x * COLS;
    const float* zr  = z   + rb;
    const float* er  = eps + rb;
    float*       orr = out + rb;

    // zero pass-1 histogram before any atomics
    #pragma unroll
    for (int q = 0; q < 4; ++q) hist[tid + q * NTHR] = 0;
    __syncthreads();

    // ---- Phase 1: load, compute keys -> smem, fused pass-1 histogram (top 11 bits)
    #pragma unroll
    for (int c = 0; c < 4; ++c) {
        int i = (c * NTHR + tid) * 4;
        float4 zv = *reinterpret_cast<const float4*>(zr + i);
        float4 ev = *reinterpret_cast<const float4*>(er + i);
        uint4 kv;
        kv.x = gm_key(zv.x, ev.x);
        kv.y = gm_key(zv.y, ev.y);
        kv.z = gm_key(zv.z, ev.z);
        kv.w = gm_key(zv.w, ev.w);
        *reinterpret_cast<uint4*>(&keys[i]) = kv;
        atomicAdd(&hist[kv.x >> 21], 1u);
        atomicAdd(&hist[kv.y >> 21], 1u);
        atomicAdd(&hist[kv.z >> 21], 1u);
        atomicAdd(&hist[kv.w >> 21], 1u);
    }
    __syncthreads();

    // ---- Pass 1 select: bits [31:21]
    select_bin<2048>(hist, KSEL, wsum, &s_bin, &s_rem, tid);
    const unsigned b1 = s_bin;
    unsigned rem = s_rem;

    // ---- Pass 2: bits [20:10] among keys with top-11 == b1
    #pragma unroll
    for (int q = 0; q < 4; ++q) hist[tid + q * NTHR] = 0;
    __syncthreads();
    #pragma unroll
    for (int j = 0; j < EPT; ++j) {
        unsigned k = keys[tid + j * NTHR];         // stride-512: bank-conflict-free
        if ((k >> 21) == b1)
            atomicAdd(&hist[(k >> 10) & 0x7FFu], 1u);
    }
    __syncthreads();
    select_bin<2048>(hist, rem, wsum, &s_bin, &s_rem, tid);
    const unsigned p21 = (b1 << 11) | s_bin;       // bits [31:10] of threshold
    rem = s_rem;

    // ---- Pass 3: bits [9:0] among keys with top-22 == p21
    #pragma unroll
    for (int q = 0; q < 2; ++q) hist[tid + q * NTHR] = 0;
    __syncthreads();
    #pragma unroll
    for (int j = 0; j < EPT; ++j) {
        unsigned k = keys[tid + j * NTHR];
        if ((k >> 10) == p21)
            atomicAdd(&hist[k & 0x3FFu], 1u);
    }
    __syncthreads();
    select_bin<1024>(hist, rem, wsum, &s_bin, &s_rem, tid);
    const unsigned t = (p21 << 10) | s_bin;        // exact K-th largest key
    const unsigned remaining = s_rem;              // #equal keys to take (lowest idx first)

    // ---- Phase 3: stable rank of equal keys (index order == chunk order)
    unsigned local_eq = 0;
    #pragma unroll
    for (int c = 0; c < 4; ++c) {
        uint4 kv = *reinterpret_cast<const uint4*>(&keys[tid * EPT + c * 4]);
        local_eq += (kv.x == t) + (kv.y == t) + (kv.z == t) + (kv.w == t);
    }
    const int lane = tid & 31, w = tid >> 5;
    unsigned inc = local_eq;
    #pragma unroll
    for (int d = 1; d < 32; d <<= 1) {
        unsigned v = __shfl_up_sync(0xFFFFFFFFu, inc, d);
        if (lane >= d) inc += v;
    }
    if (lane == 31) wsum[w] = inc;
    __syncthreads();
    if (tid < 32) {
        unsigned v = (tid < 16) ? wsum[tid] : 0u;
        #pragma unroll
        for (int d = 1; d < 16; d <<= 1) {
            unsigned u = __shfl_up_sync(0xFFFFFFFFu, v, d);
            if (tid >= d) v += u;
        }
        if (tid < 16) wsum[tid] = v;
    }
    __syncthreads();
    unsigned run = (inc - local_eq) + (w ? wsum[w - 1] : 0u);

    // ---- Phase 4: emit 0/1 mask (exact forward value of the straight-through op)
    #pragma unroll
    for (int c = 0; c < 4; ++c) {
        uint4 kv = *reinterpret_cast<const uint4*>(&keys[tid * EPT + c * 4]);
        float4 o;
        o.x = (kv.x > t || (kv.x == t && run < remaining)) ? 1.0f : 0.0f; run += (kv.x == t);
        o.y = (kv.y > t || (kv.y == t && run < remaining)) ? 1.0f : 0.0f; run += (kv.y == t);
        o.z = (kv.z > t || (kv.z == t && run < remaining)) ? 1.0f : 0.0f; run += (kv.z == t);
        o.w = (kv.w > t || (kv.w == t && run < remaining)) ? 1.0f : 0.0f; run += (kv.w == t);
        *reinterpret_cast<float4*>(orr + tid * EPT + c * 4) = o;
    }
}

extern "C" void kernel_launch(void* const* d_in, const int* in_sizes, int n_in,
                              void* d_out, int out_size)
{
    const float* z   = (const float*)d_in[0];   // z_loga  [4096, 8192] f32
    const float* eps = (const float*)d_in[1];   // eps     [4096, 8192] f32
    float* out = (float*)d_out;                 // [4096, 8192] f32
    (void)in_sizes; (void)n_in; (void)out_size;

    mask_topk_kernel<<<ROWS, NTHR>>>(z, eps, out);
}